// round 4
// baseline (speedup 1.0000x reference)
#include <cuda_runtime.h>
#include <cstdint>

// NeuralHashVoxel: counting-sorted queries (32^3 Morton bins ~= 32 queries/bin,
// i.e. one warp per spatial bin) + validity-gated two-round hash probing.
//
// Inputs: d_in[0] query_points f32 (N,3) in [0,50); d_in[1] features f32 (6,524288,8);
//         d_in[2] feature_indexs i32 (6,4194304) (-1 empty else [0,T)).
// Output: f32 (N,8).

#define NHV_L 6
#define NHV_T 524288
#define NHV_B 4194304u
#define NHV_BMASK 4194303u
#define P0 73856093u
#define P1 19349669u
#define P2 83492791u

#define NQ_MAX (1u << 20)
#define GRID1D 32
#define NBINS (GRID1D * GRID1D * GRID1D)   // 32768
#define SCAN_NBLK 32                        // 32 blocks x 1024 bins

__device__ uint32_t g_hist[NBINS];
__device__ uint32_t g_blocksum[SCAN_NBLK];
__device__ uint32_t g_perm[NQ_MAX];
__device__ float4   g_qsort[NQ_MAX];

static __device__ __forceinline__ uint32_t expand3(uint32_t x) {
    x &= 0x3FFu;
    x = (x | (x << 16)) & 0x030000FFu;
    x = (x | (x << 8))  & 0x0300F00Fu;
    x = (x | (x << 4))  & 0x030C30C3u;
    x = (x | (x << 2))  & 0x09249249u;
    return x;
}

static __device__ __forceinline__ uint32_t bin_of(float x, float y, float z) {
    const float sc = (float)GRID1D / 50.0f;
    int bx = (int)(x * sc), by = (int)(y * sc), bz = (int)(z * sc);
    bx = min(max(bx, 0), GRID1D - 1);
    by = min(max(by, 0), GRID1D - 1);
    bz = min(max(bz, 0), GRID1D - 1);
    return expand3((uint32_t)bx) | (expand3((uint32_t)by) << 1) | (expand3((uint32_t)bz) << 2);
}

__global__ void zero_hist_kernel() {
    int i = blockIdx.x * blockDim.x + threadIdx.x;
    if (i < NBINS) g_hist[i] = 0u;
}

__global__ void hist_kernel(const float* __restrict__ qp, int n) {
    int i = blockIdx.x * blockDim.x + threadIdx.x;
    if (i >= n) return;
    float x = qp[3 * i], y = qp[3 * i + 1], z = qp[3 * i + 2];
    atomicAdd(&g_hist[bin_of(x, y, z)], 1u);
}

// Per-block exclusive scan over 1024 bins; emits block total.
__global__ void __launch_bounds__(1024) scan_blocks_kernel() {
    __shared__ uint32_t sh[1024];
    int t = threadIdx.x;
    int b = blockIdx.x * 1024 + t;
    uint32_t v = g_hist[b];
    sh[t] = v;
    __syncthreads();
    #pragma unroll
    for (int off = 1; off < 1024; off <<= 1) {
        uint32_t add = (t >= off) ? sh[t - off] : 0u;
        __syncthreads();
        sh[t] += add;
        __syncthreads();
    }
    g_hist[b] = sh[t] - v;  // exclusive within block
    if (t == 1023) g_blocksum[blockIdx.x] = sh[t];
}

// Fused: compute this block's global offset (serial prefix over <=31 sums) + add.
__global__ void __launch_bounds__(1024) add_offsets_kernel() {
    __shared__ uint32_t off;
    if (threadIdx.x == 0) {
        uint32_t run = 0;
        for (int j = 0; j < (int)blockIdx.x; j++) run += g_blocksum[j];
        off = run;
    }
    __syncthreads();
    g_hist[blockIdx.x * 1024 + threadIdx.x] += off;
}

__global__ void scatter_kernel(const float* __restrict__ qp, int n) {
    int i = blockIdx.x * blockDim.x + threadIdx.x;
    if (i >= n) return;
    float x = qp[3 * i], y = qp[3 * i + 1], z = qp[3 * i + 2];
    uint32_t bin = bin_of(x, y, z);
    uint32_t pos = atomicAdd(&g_hist[bin], 1u);
    g_perm[pos] = (uint32_t)i;
    g_qsort[pos] = make_float4(x, y, z, 0.f);
}

__global__ void __launch_bounds__(256) nhv_kernel(
    const float* __restrict__ feats,
    const int*   __restrict__ fidx,
    float* __restrict__ out,
    int n_query)
{
    int i = blockIdx.x * blockDim.x + threadIdx.x;
    if (i >= n_query) return;

    const float4 q = g_qsort[i];
    const uint32_t n = g_perm[i];
    const float qx = q.x, qy = q.y, qz = q.z;

    float acc0 = 0.f, acc1 = 0.f, acc2 = 0.f, acc3 = 0.f;
    float acc4 = 0.f, acc5 = 0.f, acc6 = 0.f, acc7 = 0.f;

    float s = 4.0f;  // 1 / (0.25 * 2^lev)

    for (int lev = 0; lev < NHV_L; lev++, s *= 0.5f) {
        const float sx = qx * s, sy = qy * s, sz = qz * s;
        const float bx = floorf(sx), by = floorf(sy), bz = floorf(sz);
        const float tx = sx - bx, ty = sy - by, tz = sz - bz;

        const uint32_t ix = (uint32_t)(int)bx;
        const uint32_t iy = (uint32_t)(int)by;
        const uint32_t iz = (uint32_t)(int)bz;
        const uint32_t h0 = ix * P0 + iy * P1 + iz * P2;

        const int* __restrict__ htab = fidx + (size_t)lev * NHV_B;

        // Round 1: probe 4 corners (x-low face). P(all valid) = 0.41 gates round 2.
        int idx[8];
        #pragma unroll
        for (int k = 0; k < 4; k++) {
            uint32_t key = h0;
            if (k & 2) key += P1;
            if (k & 1) key += P2;
            key &= NHV_BMASK;
            idx[k] = __ldg(htab + key);
        }
        int v4 = idx[0] | idx[1] | idx[2] | idx[3];
        if (v4 < 0) continue;   // lane skips round 2 + features (no wavefronts)

        // Round 2: remaining 4 corners.
        #pragma unroll
        for (int k = 4; k < 8; k++) {
            uint32_t key = h0 + P0;
            if (k & 2) key += P1;
            if (k & 1) key += P2;
            key &= NHV_BMASK;
            idx[k] = __ldg(htab + key);
        }
        int allv = v4 | idx[4] | idx[5] | idx[6] | idx[7];
        if (allv < 0) continue;

        const float wxa[2] = { 1.f - tx, tx };
        const float wya[2] = { 1.f - ty, ty };
        const float wza[2] = { 1.f - tz, tz };

        const float* __restrict__ ftab = feats + (size_t)lev * NHV_T * 8;

        #pragma unroll
        for (int k = 0; k < 8; k++) {
            const float w = wxa[(k >> 2) & 1] * wya[(k >> 1) & 1] * wza[k & 1];
            uint32_t id = (uint32_t)idx[k];
            id = (id < NHV_T) ? id : (NHV_T - 1u);
            const float4* fp = (const float4*)(ftab + ((size_t)id << 3));
            float4 a = __ldg(fp);
            float4 b = __ldg(fp + 1);
            acc0 = fmaf(w, a.x, acc0);
            acc1 = fmaf(w, a.y, acc1);
            acc2 = fmaf(w, a.z, acc2);
            acc3 = fmaf(w, a.w, acc3);
            acc4 = fmaf(w, b.x, acc4);
            acc5 = fmaf(w, b.y, acc5);
            acc6 = fmaf(w, b.z, acc6);
            acc7 = fmaf(w, b.w, acc7);
        }
    }

    float4* o = (float4*)(out + ((size_t)n << 3));
    o[0] = make_float4(acc0, acc1, acc2, acc3);
    o[1] = make_float4(acc4, acc5, acc6, acc7);
}

extern "C" void kernel_launch(void* const* d_in, const int* in_sizes, int n_in,
                              void* d_out, int out_size)
{
    const float* qp    = (const float*)d_in[0];
    const float* feats = (const float*)d_in[1];
    const int*   fidx  = (const int*)d_in[2];
    float* out = (float*)d_out;

    int n_query = in_sizes[0] / 3;
    int threads = 256;
    int blocks = (n_query + threads - 1) / threads;

    zero_hist_kernel<<<(NBINS + 255) / 256, 256>>>();
    hist_kernel<<<blocks, threads>>>(qp, n_query);
    scan_blocks_kernel<<<SCAN_NBLK, 1024>>>();
    add_offsets_kernel<<<SCAN_NBLK, 1024>>>();
    scatter_kernel<<<blocks, threads>>>(qp, n_query);
    nhv_kernel<<<blocks, threads>>>(feats, fidx, out, n_query);
}

// round 7
// speedup vs baseline: 1.1395x; 1.1395x over previous
#include <cuda_runtime.h>
#include <cstdint>

// NeuralHashVoxel: 64^3-Morton counting-sorted queries + per-level hash probing.
// Levels 0-1 (spatially scattered lanes): two-round validity-gated probing.
// Levels 2-5 (post-sort coalesced): single-round 8-probe (gating saves nothing).
//
// Inputs: d_in[0] query_points f32 (N,3) in [0,50); d_in[1] features f32 (6,524288,8);
//         d_in[2] feature_indexs i32 (6,4194304) (-1 empty else [0,T)).
// Output: f32 (N,8).

#define NHV_L 6
#define NHV_T 524288
#define NHV_B 4194304u
#define NHV_BMASK 4194303u
#define P0 73856093u
#define P1 19349669u
#define P2 83492791u

#define NQ_MAX (1u << 20)
#define GRID1D 64
#define NBINS (GRID1D * GRID1D * GRID1D)     // 262144
#define SCAN_BLOCK_BINS 1024
#define SCAN_NBLK (NBINS / SCAN_BLOCK_BINS)  // 256

__device__ uint32_t g_hist[NBINS];
__device__ uint32_t g_blocksum[SCAN_NBLK];
__device__ uint32_t g_perm[NQ_MAX];
__device__ float4   g_qsort[NQ_MAX];

static __device__ __forceinline__ uint32_t expand3(uint32_t x) {
    x &= 0x3FFu;
    x = (x | (x << 16)) & 0x030000FFu;
    x = (x | (x << 8))  & 0x0300F00Fu;
    x = (x | (x << 4))  & 0x030C30C3u;
    x = (x | (x << 2))  & 0x09249249u;
    return x;
}

static __device__ __forceinline__ uint32_t bin_of(float x, float y, float z) {
    const float sc = (float)GRID1D / 50.0f;
    int bx = (int)(x * sc), by = (int)(y * sc), bz = (int)(z * sc);
    bx = min(max(bx, 0), GRID1D - 1);
    by = min(max(by, 0), GRID1D - 1);
    bz = min(max(bz, 0), GRID1D - 1);
    return expand3((uint32_t)bx) | (expand3((uint32_t)by) << 1) | (expand3((uint32_t)bz) << 2);
}

__global__ void zero_hist_kernel() {
    int i = blockIdx.x * blockDim.x + threadIdx.x;
    if (i < NBINS) g_hist[i] = 0u;
}

__global__ void hist_kernel(const float* __restrict__ qp, int n) {
    int i = blockIdx.x * blockDim.x + threadIdx.x;
    if (i >= n) return;
    float x = qp[3 * i], y = qp[3 * i + 1], z = qp[3 * i + 2];
    atomicAdd(&g_hist[bin_of(x, y, z)], 1u);
}

// Per-block exclusive scan over 1024 bins; emits block total.
__global__ void __launch_bounds__(SCAN_BLOCK_BINS) scan_blocks_kernel() {
    __shared__ uint32_t sh[SCAN_BLOCK_BINS];
    int t = threadIdx.x;
    int b = blockIdx.x * SCAN_BLOCK_BINS + t;
    uint32_t v = g_hist[b];
    sh[t] = v;
    __syncthreads();
    #pragma unroll
    for (int off = 1; off < SCAN_BLOCK_BINS; off <<= 1) {
        uint32_t add = (t >= off) ? sh[t - off] : 0u;
        __syncthreads();
        sh[t] += add;
        __syncthreads();
    }
    g_hist[b] = sh[t] - v;  // exclusive within block
    if (t == SCAN_BLOCK_BINS - 1) g_blocksum[blockIdx.x] = sh[t];
}

// Fused: every block redundantly scans the 256 block sums (cheap, L2-resident),
// picks its own exclusive offset, adds to its 1024 bins. Saves one launch.
__global__ void __launch_bounds__(SCAN_BLOCK_BINS) add_offsets_kernel() {
    __shared__ uint32_t sh[SCAN_NBLK];
    int t = threadIdx.x;
    if (t < SCAN_NBLK) sh[t] = g_blocksum[t];
    __syncthreads();
    // Hillis-Steele inclusive scan over 256 entries (first 256 threads).
    #pragma unroll
    for (int off = 1; off < SCAN_NBLK; off <<= 1) {
        uint32_t add = (t < SCAN_NBLK && t >= off) ? sh[t - off] : 0u;
        __syncthreads();
        if (t < SCAN_NBLK) sh[t] += add;
        __syncthreads();
    }
    uint32_t off = (blockIdx.x == 0) ? 0u : sh[blockIdx.x - 1];
    g_hist[blockIdx.x * SCAN_BLOCK_BINS + t] += off;
}

__global__ void scatter_kernel(const float* __restrict__ qp, int n) {
    int i = blockIdx.x * blockDim.x + threadIdx.x;
    if (i >= n) return;
    float x = qp[3 * i], y = qp[3 * i + 1], z = qp[3 * i + 2];
    uint32_t bin = bin_of(x, y, z);
    uint32_t pos = atomicAdd(&g_hist[bin], 1u);
    g_perm[pos] = (uint32_t)i;
    g_qsort[pos] = make_float4(x, y, z, 0.f);
}

// One resolution level. GATE: probe 4 corners, test, then the other 4
// (saves wavefronts only when lanes are spatially scattered, i.e. fine levels).
template <bool GATE>
static __device__ __forceinline__ void do_level(
    float sx, float sy, float sz,
    const int* __restrict__ htab,
    const float* __restrict__ ftab,
    float* __restrict__ acc)
{
    const float bx = floorf(sx), by = floorf(sy), bz = floorf(sz);
    const float tx = sx - bx, ty = sy - by, tz = sz - bz;

    const uint32_t ix = (uint32_t)(int)bx;
    const uint32_t iy = (uint32_t)(int)by;
    const uint32_t iz = (uint32_t)(int)bz;
    const uint32_t h0 = ix * P0 + iy * P1 + iz * P2;

    int idx[8];
    if (GATE) {
        #pragma unroll
        for (int k = 0; k < 4; k++) {
            uint32_t key = h0;
            if (k & 2) key += P1;
            if (k & 1) key += P2;
            idx[k] = __ldg(htab + (key & NHV_BMASK));
        }
        if ((idx[0] | idx[1] | idx[2] | idx[3]) < 0) return;
        #pragma unroll
        for (int k = 4; k < 8; k++) {
            uint32_t key = h0 + P0;
            if (k & 2) key += P1;
            if (k & 1) key += P2;
            idx[k] = __ldg(htab + (key & NHV_BMASK));
        }
        if ((idx[4] | idx[5] | idx[6] | idx[7]) < 0) return;
    } else {
        #pragma unroll
        for (int k = 0; k < 8; k++) {
            uint32_t key = h0;
            if (k & 4) key += P0;
            if (k & 2) key += P1;
            if (k & 1) key += P2;
            idx[k] = __ldg(htab + (key & NHV_BMASK));
        }
        if ((idx[0] | idx[1] | idx[2] | idx[3] |
             idx[4] | idx[5] | idx[6] | idx[7]) < 0) return;
    }

    const float wxa[2] = { 1.f - tx, tx };
    const float wya[2] = { 1.f - ty, ty };
    const float wza[2] = { 1.f - tz, tz };

    #pragma unroll
    for (int k = 0; k < 8; k++) {
        const float w = wxa[(k >> 2) & 1] * wya[(k >> 1) & 1] * wza[k & 1];
        uint32_t id = (uint32_t)idx[k];
        id = (id < NHV_T) ? id : (NHV_T - 1u);
        const float4* fp = (const float4*)(ftab + ((size_t)id << 3));
        float4 a = __ldg(fp);
        float4 b = __ldg(fp + 1);
        acc[0] = fmaf(w, a.x, acc[0]);
        acc[1] = fmaf(w, a.y, acc[1]);
        acc[2] = fmaf(w, a.z, acc[2]);
        acc[3] = fmaf(w, a.w, acc[3]);
        acc[4] = fmaf(w, b.x, acc[4]);
        acc[5] = fmaf(w, b.y, acc[5]);
        acc[6] = fmaf(w, b.z, acc[6]);
        acc[7] = fmaf(w, b.w, acc[7]);
    }
}

__global__ void __launch_bounds__(256) nhv_kernel(
    const float* __restrict__ feats,
    const int*   __restrict__ fidx,
    float* __restrict__ out,
    int n_query)
{
    int i = blockIdx.x * blockDim.x + threadIdx.x;
    if (i >= n_query) return;

    const float4 q = g_qsort[i];
    const uint32_t n = g_perm[i];

    float acc[8] = {0.f, 0.f, 0.f, 0.f, 0.f, 0.f, 0.f, 0.f};

    const size_t HB = (size_t)NHV_B;
    const size_t FT = (size_t)NHV_T * 8;

    // lev 0..5, scale = 4 / 2^lev; GATE only on the scattered fine levels.
    do_level<true >(q.x * 4.f,    q.y * 4.f,    q.z * 4.f,    fidx,          feats,          acc);
    do_level<true >(q.x * 2.f,    q.y * 2.f,    q.z * 2.f,    fidx + HB,     feats + FT,     acc);
    do_level<false>(q.x * 1.f,    q.y * 1.f,    q.z * 1.f,    fidx + 2*HB,   feats + 2*FT,   acc);
    do_level<false>(q.x * 0.5f,   q.y * 0.5f,   q.z * 0.5f,   fidx + 3*HB,   feats + 3*FT,   acc);
    do_level<false>(q.x * 0.25f,  q.y * 0.25f,  q.z * 0.25f,  fidx + 4*HB,   feats + 4*FT,   acc);
    do_level<false>(q.x * 0.125f, q.y * 0.125f, q.z * 0.125f, fidx + 5*HB,   feats + 5*FT,   acc);

    float4* o = (float4*)(out + ((size_t)n << 3));
    o[0] = make_float4(acc[0], acc[1], acc[2], acc[3]);
    o[1] = make_float4(acc[4], acc[5], acc[6], acc[7]);
}

extern "C" void kernel_launch(void* const* d_in, const int* in_sizes, int n_in,
                              void* d_out, int out_size)
{
    const float* qp    = (const float*)d_in[0];
    const float* feats = (const float*)d_in[1];
    const int*   fidx  = (const int*)d_in[2];
    float* out = (float*)d_out;

    int n_query = in_sizes[0] / 3;
    int threads = 256;
    int blocks = (n_query + threads - 1) / threads;

    zero_hist_kernel<<<(NBINS + 255) / 256, 256>>>();
    hist_kernel<<<blocks, threads>>>(qp, n_query);
    scan_blocks_kernel<<<SCAN_NBLK, SCAN_BLOCK_BINS>>>();
    add_offsets_kernel<<<SCAN_NBLK, SCAN_BLOCK_BINS>>>();
    scatter_kernel<<<blocks, threads>>>(qp, n_query);
    nhv_kernel<<<blocks, threads>>>(feats, fidx, out, n_query);
}